// round 11
// baseline (speedup 1.0000x reference)
#include <cuda_runtime.h>
#include <cuda_bf16.h>
#include <cstdint>

// ---------------------------------------------------------------------------
// StableSpikingCoreFlow, round 11.
// Layer 0: unchanged from round 10 (interleaved-slot bf16 HMMA, splitK=4,
//          planes + scan) - measured rel_err 0.0.
// Layers 1-3: ONE fused kernel per layer: full-K 128m x 16n blocks, A =
//          counts (exact bf16), W split to 3 bf16 pieces IN-KERNEL from fp32
//          (read once), per-phase Kahan folds (64-col chunks, same class as
//          round 10), spike scan fused into the epilogue. No B pieces in
//          DRAM, no splitK planes, no scan kernel.
// ---------------------------------------------------------------------------

#define Bc 128
#define Dc 2048
#define Nc 2048
#define Tc 64
#define OUTc 1024
#define SPLITK 4

#define KT0 12288            // layer-0 interleaved slot count
#define GT  256

#define ROWB 144             // 64 bf16 (128B) + 16B pad
#define ATILE (128 * ROWB)   // 18432 B
#define BTILE0 (64 * ROWB)   //  9216 B
#define BUF0  (ATILE + BTILE0)
#define SMEM0 (2 * BUF0)     // 55296 B

// fused layers>=1 kernel smem
#define BPIECE (16 * ROWB)           // 2304 B
#define BTILEF (3 * BPIECE)          // 6912 B
#define BUFF   (ATILE + BTILEF)      // 25344 B
#define SMEMF  (2 * BUFF)            // 50688 B

__device__ __nv_bfloat16 g_A[(size_t)Bc * KT0];
__device__ __nv_bfloat16 g_B[(size_t)Nc * KT0];
__device__ float g_P[SPLITK * Bc * Nc];
__device__ float g_R0[Bc * Nc];
__device__ float g_R1[Bc * Nc];

// ---------------------------------------------------------------------------
__device__ __forceinline__ void cp16(uint32_t dst, const void* src) {
    asm volatile("cp.async.cg.shared.global [%0], [%1], 16;\n" :: "r"(dst), "l"(src));
}
#define CP_COMMIT() asm volatile("cp.async.commit_group;\n" ::: "memory")
#define CP_WAIT(n)  asm volatile("cp.async.wait_group %0;\n" :: "n"(n) : "memory")

__device__ __forceinline__ void mma16816(float* c, const uint32_t* a,
                                         uint32_t b0, uint32_t b1) {
    asm volatile(
        "mma.sync.aligned.m16n8k16.row.col.f32.bf16.bf16.f32 "
        "{%0,%1,%2,%3},{%4,%5,%6,%7},{%8,%9},{%0,%1,%2,%3};\n"
        : "+f"(c[0]), "+f"(c[1]), "+f"(c[2]), "+f"(c[3])
        : "r"(a[0]), "r"(a[1]), "r"(a[2]), "r"(a[3]), "r"(b0), "r"(b1));
}

__device__ __forceinline__ uint32_t lds32c(const char* p) {
    return *(const uint32_t*)p;
}

__device__ __forceinline__ float bfround(float v) {
    return __bfloat162float(__float2bfloat16_rn(v));
}
__device__ __forceinline__ unsigned bfu(float v) {
    return (unsigned)__bfloat16_as_ushort(__float2bfloat16_rn(v));
}
__device__ __forceinline__ uint32_t pk(unsigned lo, unsigned hi) {
    return lo | (hi << 16);
}
// v = p0+p1+p2 + O(2^-25 v); residual subtractions exact
__device__ __forceinline__ void split3(float v, unsigned& u0, unsigned& u1,
                                       unsigned& u2) {
    float r1 = v - bfround(v);
    float r2 = r1 - bfround(r1);
    u0 = bfu(v); u1 = bfu(r1); u2 = bfu(r2);
}

// exact fp32 semantics of the reference spike scan; returns COUNT (0..64)
__device__ __forceinline__ float spike_count(float a, float thr) {
    int c;
    if (a <= 0.f) c = 0;
    else if (a > thr) c = Tc;
    else {
        float m = 0.f; c = 0;
        for (int t = 0; t < Tc; t++) { m += a; if (m > thr) { m -= thr; c++; } }
    }
    return (float)c;
}

// ---------------------------------------------------------------------------
// layer-0 prep: A' slots [v0,v0,v0,v1,v1,v2] of v=64*x gathered; B' slots
// [w0,w1,w2,w0,w1,w0]  (pairs (0,0)(0,1)(0,2)(1,0)(1,1)(2,0)).
__global__ void prep0_kernel(const float* __restrict__ x,
                             const int* __restrict__ axon,
                             const float* __restrict__ W) {
    int idx = blockIdx.x * blockDim.x + threadIdx.x;
    if (idx < Bc * Dc) {
        int b = idx >> 11, a = idx & 2047;
        unsigned u0, u1, u2;
        split3(64.0f * x[(b << 11) + axon[a]], u0, u1, u2);
        uint32_t* dst = (uint32_t*)(g_A + (size_t)b * KT0 + 6 * a);
        dst[0] = pk(u0, u0); dst[1] = pk(u0, u1); dst[2] = pk(u1, u2);
    } else {
        int i = idx - Bc * Dc;
        if (i >= Nc * Dc) return;
        int n = i >> 11, k = i & 2047;
        unsigned u0, u1, u2;
        split3(W[i], u0, u1, u2);
        uint32_t* dst = (uint32_t*)(g_B + (size_t)n * KT0 + 6 * k);
        dst[0] = pk(u0, u1); dst[1] = pk(u2, u0); dst[2] = pk(u1, u0);
    }
}

// layers>=1 prep: gather counts only (exact bf16), A at K=2048
__global__ void prep1g_kernel(const float* __restrict__ R,
                              const int* __restrict__ axon) {
    int idx = blockIdx.x * blockDim.x + threadIdx.x;
    if (idx >= Bc * Dc / 2) return;
    int b = idx >> 10, a = (idx & 1023) * 2;
    unsigned h0 = bfu(R[(b << 11) + axon[a]]);
    unsigned h1 = bfu(R[(b << 11) + axon[a + 1]]);
    *(uint32_t*)(g_A + (size_t)b * Dc + a) = pk(h0, h1);
}

// ---------------------------------------------------------------------------
// layer-0 GEMM (unchanged from round 10): interleaved slots, Ktot=12288,
// splitK=4 (slice 3072, 48 phases of 64 slots), Kahan fold every 2 phases.
__global__ __launch_bounds__(GT, 1)
void gemm0_kernel() {
    extern __shared__ char smch[];
    const int tid = threadIdx.x;
    const int w = tid >> 5, lane = tid & 31;
    const int wm = w & 3, wn = w >> 2;
    const int g = lane >> 2, tig = lane & 3;
    const int bn = blockIdx.x * 64;
    const size_t k0 = (size_t)blockIdx.y * (KT0 / SPLITK);
    const uint32_t smb = (uint32_t)__cvta_generic_to_shared(smch);
    const int nPh = (KT0 / SPLITK) / 64;   // 48

    const __nv_bfloat16* srcs[6];
    uint32_t dsts[6];
    const int ch = tid & 7;
#pragma unroll
    for (int r = 0; r < 4; r++) {
        int row = (tid + r * GT) >> 3;
        srcs[r] = g_A + (size_t)row * KT0 + k0 + ch * 8;
        dsts[r] = smb + row * ROWB + ch * 16;
    }
#pragma unroll
    for (int r = 4; r < 6; r++) {
        int brow = (tid + (r - 4) * GT) >> 3;
        srcs[r] = g_B + (size_t)(bn + brow) * KT0 + k0 + ch * 8;
        dsts[r] = smb + ATILE + brow * ROWB + ch * 16;
    }
#define G0ISSUE(p, buf) do {                                        \
        uint32_t bo = (uint32_t)(buf) * BUF0;                       \
        _Pragma("unroll")                                           \
        for (int r = 0; r < 6; r++)                                 \
            cp16(dsts[r] + bo, srcs[r] + (size_t)(p) * 64);         \
        CP_COMMIT();                                                \
    } while (0)

    float acc[2][4][4], ks[2][4][4], kc[2][4][4];
#pragma unroll
    for (int mt = 0; mt < 2; mt++)
#pragma unroll
        for (int j = 0; j < 4; j++)
#pragma unroll
            for (int q = 0; q < 4; q++) {
                acc[mt][j][q] = 0.f; ks[mt][j][q] = 0.f; kc[mt][j][q] = 0.f;
            }

    G0ISSUE(0, 0);
    G0ISSUE(1, 1);

    for (int p = 0; p < nPh; p++) {
        if (p + 1 < nPh) { CP_WAIT(1); } else { CP_WAIT(0); }
        __syncthreads();
        const char* Ab = smch + (p & 1) * BUF0;
        const char* Bb = Ab + ATILE;
#pragma unroll
        for (int kk = 0; kk < 4; kk++) {
            uint32_t a[2][4];
#pragma unroll
            for (int mt = 0; mt < 2; mt++) {
                const char* ap = Ab + (wm * 32 + mt * 16 + g) * ROWB
                               + kk * 32 + tig * 4;
                a[mt][0] = lds32c(ap);
                a[mt][1] = lds32c(ap + 8 * ROWB);
                a[mt][2] = lds32c(ap + 16);
                a[mt][3] = lds32c(ap + 8 * ROWB + 16);
            }
#pragma unroll
            for (int j = 0; j < 4; j++) {
                const char* bp = Bb + (wn * 32 + j * 8 + g) * ROWB
                               + kk * 32 + tig * 4;
                uint32_t b0 = lds32c(bp);
                uint32_t b1 = lds32c(bp + 16);
                mma16816(acc[0][j], a[0], b0, b1);
                mma16816(acc[1][j], a[1], b0, b1);
            }
        }
        __syncthreads();
        if (p + 2 < nPh) G0ISSUE(p + 2, p & 1);

        if (p & 1) {
#pragma unroll
            for (int mt = 0; mt < 2; mt++)
#pragma unroll
                for (int j = 0; j < 4; j++)
#pragma unroll
                    for (int q = 0; q < 4; q++) {
                        float y = __fsub_rn(acc[mt][j][q], kc[mt][j][q]);
                        float t = __fadd_rn(ks[mt][j][q], y);
                        kc[mt][j][q] = __fsub_rn(__fsub_rn(t, ks[mt][j][q]), y);
                        ks[mt][j][q] = t;
                        acc[mt][j][q] = 0.f;
                    }
        }
    }
#undef G0ISSUE

    float* plane = g_P + (size_t)blockIdx.y * (Bc * Nc);
#pragma unroll
    for (int mt = 0; mt < 2; mt++)
#pragma unroll
        for (int j = 0; j < 4; j++) {
            int m = wm * 32 + mt * 16 + g;
            int n = bn + wn * 32 + j * 8 + 2 * tig;
            float r0 = __fsub_rn(ks[mt][j][0], kc[mt][j][0]);
            float r1 = __fsub_rn(ks[mt][j][1], kc[mt][j][1]);
            float r2 = __fsub_rn(ks[mt][j][2], kc[mt][j][2]);
            float r3 = __fsub_rn(ks[mt][j][3], kc[mt][j][3]);
            *(float2*)&plane[(size_t)m * Nc + n]       = make_float2(r0, r1);
            *(float2*)&plane[(size_t)(m + 8) * Nc + n] = make_float2(r2, r3);
        }
}

// ---------------------------------------------------------------------------
// layers>=1 FUSED kernel: full K=2048, block 128m x 16n (grid 128), 8 warps
// (warp tile 16m x 16n). A = counts via cp.async; W fp32 loaded once, split
// to 3 bf16 piece tiles in-kernel. Kahan fold every 64-col phase; spike scan
// fused in the epilogue, writes counts to R.
__global__ __launch_bounds__(GT)
void gemm1f_kernel(const float* __restrict__ W,     // this layer, [N][D] fp32
                   const float* __restrict__ thr, int l,
                   float* __restrict__ R) {
    extern __shared__ char smch[];
    const int tid = threadIdx.x;
    const int w = tid >> 5, lane = tid & 31;
    const int g = lane >> 2, tig = lane & 3;
    const int bn = blockIdx.x * 16;
    const uint32_t smb = (uint32_t)__cvta_generic_to_shared(smch);
    const int nPh = Dc / 64;   // 32

    // A cp.async mapping: 1024 chunks, 4 per thread
    const int ch = tid & 7;
    const __nv_bfloat16* sA[4];
    uint32_t dA[4];
#pragma unroll
    for (int r = 0; r < 4; r++) {
        int row = (tid >> 3) + 32 * r;
        sA[r] = g_A + (size_t)row * Dc + ch * 8;
        dA[r] = smb + row * ROWB + ch * 16;
    }

    // B: W fp32, 16 rows x 64 cols per phase; 1 float4 per thread
    const int brow = tid >> 4;          // 0..15
    const int bcol = (tid & 15) * 4;    // 0..60
    const float* wp = W + (size_t)(bn + brow) * Dc + bcol;
    const uint32_t bsts = smb + ATILE + brow * ROWB + bcol * 2;

#define FA(p, buf) do {                                             \
        uint32_t bo = (uint32_t)(buf) * BUFF;                       \
        _Pragma("unroll")                                           \
        for (int r = 0; r < 4; r++)                                 \
            cp16(dA[r] + bo, sA[r] + (size_t)(p) * 64);             \
        CP_COMMIT();                                                \
    } while (0)

#define FB(buf, v) do {                                             \
        unsigned q0[4], q1[4], q2[4];                               \
        float e4[4] = {(v).x, (v).y, (v).z, (v).w};                 \
        _Pragma("unroll")                                           \
        for (int i = 0; i < 4; i++) split3(e4[i], q0[i], q1[i], q2[i]); \
        uint32_t ba = bsts + (uint32_t)(buf) * BUFF;                \
        asm volatile("st.shared.v2.b32 [%0], {%1,%2};\n"            \
            :: "r"(ba), "r"(pk(q0[0], q0[1])), "r"(pk(q0[2], q0[3]))); \
        asm volatile("st.shared.v2.b32 [%0], {%1,%2};\n"            \
            :: "r"(ba + BPIECE), "r"(pk(q1[0], q1[1])), "r"(pk(q1[2], q1[3]))); \
        asm volatile("st.shared.v2.b32 [%0], {%1,%2};\n"            \
            :: "r"(ba + 2 * BPIECE), "r"(pk(q2[0], q2[1])), "r"(pk(q2[2], q2[3]))); \
    } while (0)

    float acc[2][4], ks[2][4], kc[2][4];
#pragma unroll
    for (int j = 0; j < 2; j++)
#pragma unroll
        for (int q = 0; q < 4; q++) {
            acc[j][q] = 0.f; ks[j][q] = 0.f; kc[j][q] = 0.f;
        }

    // prologue: phases 0 and 1 staged
    float4 wreg = *(const float4*)(wp);
    FB(0, wreg);
    FA(0, 0);
    wreg = *(const float4*)(wp + 64);
    FB(1, wreg);
    FA(1, 1);
    wreg = *(const float4*)(wp + 128);   // nPh=32 > 2 always

    for (int p = 0; p < nPh; p++) {
        if (p + 1 < nPh) { CP_WAIT(1); } else { CP_WAIT(0); }
        __syncthreads();
        const char* Ab = smch + (p & 1) * BUFF;
        const char* Bb = Ab + ATILE;
#pragma unroll
        for (int kk = 0; kk < 4; kk++) {
            uint32_t a[4];
            const char* ap = Ab + (16 * w + g) * ROWB + kk * 32 + tig * 4;
            a[0] = lds32c(ap);
            a[1] = lds32c(ap + 8 * ROWB);
            a[2] = lds32c(ap + 16);
            a[3] = lds32c(ap + 8 * ROWB + 16);
#pragma unroll
            for (int pc = 0; pc < 3; pc++) {
#pragma unroll
                for (int j = 0; j < 2; j++) {
                    const char* bp = Bb + pc * BPIECE + (j * 8 + g) * ROWB
                                   + kk * 32 + tig * 4;
                    uint32_t b0 = lds32c(bp);
                    uint32_t b1 = lds32c(bp + 16);
                    mma16816(acc[j], a, b0, b1);
                }
            }
        }
        __syncthreads();
        if (p + 2 < nPh) {
            FB(p & 1, wreg);          // stage phase p+2 into buf (p&1)
            FA(p + 2, p & 1);
            if (p + 3 < nPh) wreg = *(const float4*)(wp + (p + 3) * 64);
        }

        // Kahan fold every phase (chunk = 64 main products + corrections)
#pragma unroll
        for (int j = 0; j < 2; j++)
#pragma unroll
            for (int q = 0; q < 4; q++) {
                float y = __fsub_rn(acc[j][q], kc[j][q]);
                float t = __fadd_rn(ks[j][q], y);
                kc[j][q] = __fsub_rn(__fsub_rn(t, ks[j][q]), y);
                ks[j][q] = t;
                acc[j][q] = 0.f;
            }
    }
#undef FA
#undef FB

    // epilogue: /64 (exact) + spike scan, write counts
    const float thrl = thr[l];
#pragma unroll
    for (int j = 0; j < 2; j++)
#pragma unroll
        for (int q = 0; q < 4; q++) {
            float v = __fsub_rn(ks[j][q], kc[j][q]);
            float cnt = spike_count(v * 0.015625f, thrl);
            int m = 16 * w + g + ((q >> 1) << 3);
            int n = bn + j * 8 + 2 * tig + (q & 1);
            R[(size_t)m * Nc + n] = cnt;
        }
}

// ---------------------------------------------------------------------------
__global__ void scan_kernel(const float* __restrict__ thr, int l,
                            float* __restrict__ R) {
    int idx = blockIdx.x * blockDim.x + threadIdx.x;
    if (idx >= Bc * Nc) return;
    float e0 = g_P[0 * (Bc * Nc) + idx];
    float e1 = g_P[1 * (Bc * Nc) + idx];
    float e2 = g_P[2 * (Bc * Nc) + idx];
    float e3 = g_P[3 * (Bc * Nc) + idx];
    float s = __fadd_rn(__fadd_rn(e0, e1), __fadd_rn(e2, e3));
    R[idx] = spike_count(s * 0.015625f, thr[l]);   // /64 exact
}

__global__ void out_kernel(const float* __restrict__ R,
                           const int* __restrict__ out_idx,
                           float* __restrict__ out) {
    int idx = blockIdx.x * blockDim.x + threadIdx.x;
    if (idx >= Bc * OUTc) return;
    int b = idx >> 10, o = idx & 1023;
    out[idx] = R[(b << 11) + out_idx[o]];          // already counts
}

// ---------------------------------------------------------------------------
extern "C" void kernel_launch(void* const* d_in, const int* in_sizes, int n_in,
                              void* d_out, int out_size)
{
    const float* x       = (const float*)d_in[0];
    const float* W       = (const float*)d_in[1];
    const float* thr     = (const float*)d_in[2];
    const int*   axon    = (const int*)  d_in[3];
    const int*   out_idx = (const int*)  d_in[4];
    (void)in_sizes; (void)n_in; (void)out_size;

    cudaFuncSetAttribute(gemm0_kernel,
                         cudaFuncAttributeMaxDynamicSharedMemorySize, SMEM0);
    cudaFuncSetAttribute(gemm1f_kernel,
                         cudaFuncAttributeMaxDynamicSharedMemorySize, SMEMF);

    float *R0, *R1;
    cudaGetSymbolAddress((void**)&R0, g_R0);
    cudaGetSymbolAddress((void**)&R1, g_R1);

    // layer 0 (round-10 path, measured rel_err 0.0)
    prep0_kernel<<<(Bc * Dc + Nc * Dc + 255) / 256, 256>>>(x, axon, W);
    gemm0_kernel<<<dim3(32, SPLITK), GT, SMEM0>>>();
    scan_kernel<<<1024, 256>>>(thr, 0, R0);

    const float* rin = R0;
    for (int l = 1; l < 4; l++) {
        prep1g_kernel<<<512, 256>>>(rin, axon + l * Dc);
        float* rout = (l & 1) ? R1 : R0;
        gemm1f_kernel<<<128, GT, SMEMF>>>(W + (size_t)l * Nc * Dc, thr, l, rout);
        rin = rout;
    }
    out_kernel<<<512, 256>>>(rin, out_idx, (float*)d_out);
}

// round 12
// speedup vs baseline: 1.2054x; 1.2054x over previous
#include <cuda_runtime.h>
#include <cuda_bf16.h>
#include <cstdint>

// ---------------------------------------------------------------------------
// StableSpikingCoreFlow, round 12 = round 10 (148.2us, rel_err 0.0) with ONE
// change: layers>=1 GEMM loads W fp32 directly (each element exactly once,
// since n-blocks x k-slices partition W) and splits to 3 bf16 pieces
// in-kernel into the SAME smem layout round 10 used. MMA order, Kahan folds,
// scan: bit-identical to round 10. prep1 becomes gather-only.
// ---------------------------------------------------------------------------

#define Bc 128
#define Dc 2048
#define Nc 2048
#define Tc 64
#define OUTc 1024
#define SPLITK 4

#define KT0 12288            // layer-0 interleaved slot count
#define GT  256

#define ROWB 144             // 64 bf16 (128B) + 16B pad
#define ATILE (128 * ROWB)   // 18432 B
#define BTILE0 (64 * ROWB)   //  9216 B
#define BUF0  (ATILE + BTILE0)
#define SMEM0 (2 * BUF0)     // 55296 B
#define BTILE1 (3 * 64 * ROWB)
#define BUF1  (ATILE + BTILE1)
#define SMEM1 (2 * BUF1)     // 92160 B

__device__ __nv_bfloat16 g_A[(size_t)Bc * KT0];
__device__ __nv_bfloat16 g_B[(size_t)Nc * KT0];
__device__ float g_P[SPLITK * Bc * Nc];
__device__ float g_R0[Bc * Nc];
__device__ float g_R1[Bc * Nc];

// ---------------------------------------------------------------------------
__device__ __forceinline__ void cp16(uint32_t dst, const void* src) {
    asm volatile("cp.async.cg.shared.global [%0], [%1], 16;\n" :: "r"(dst), "l"(src));
}
#define CP_COMMIT() asm volatile("cp.async.commit_group;\n" ::: "memory")
#define CP_WAIT(n)  asm volatile("cp.async.wait_group %0;\n" :: "n"(n) : "memory")

__device__ __forceinline__ void mma16816(float* c, const uint32_t* a,
                                         uint32_t b0, uint32_t b1) {
    asm volatile(
        "mma.sync.aligned.m16n8k16.row.col.f32.bf16.bf16.f32 "
        "{%0,%1,%2,%3},{%4,%5,%6,%7},{%8,%9},{%0,%1,%2,%3};\n"
        : "+f"(c[0]), "+f"(c[1]), "+f"(c[2]), "+f"(c[3])
        : "r"(a[0]), "r"(a[1]), "r"(a[2]), "r"(a[3]), "r"(b0), "r"(b1));
}

__device__ __forceinline__ uint32_t lds32c(const char* p) {
    return *(const uint32_t*)p;
}

__device__ __forceinline__ float bfround(float v) {
    return __bfloat162float(__float2bfloat16_rn(v));
}
__device__ __forceinline__ unsigned bfu(float v) {
    return (unsigned)__bfloat16_as_ushort(__float2bfloat16_rn(v));
}
__device__ __forceinline__ uint32_t pk(unsigned lo, unsigned hi) {
    return lo | (hi << 16);
}
// v = p0+p1+p2 + O(2^-25 v); residual subtractions exact
__device__ __forceinline__ void split3(float v, unsigned& u0, unsigned& u1,
                                       unsigned& u2) {
    float r1 = v - bfround(v);
    float r2 = r1 - bfround(r1);
    u0 = bfu(v); u1 = bfu(r1); u2 = bfu(r2);
}

// exact fp32 semantics of the reference spike scan; returns COUNT (0..64)
__device__ __forceinline__ float spike_count(float a, float thr) {
    int c;
    if (a <= 0.f) c = 0;
    else if (a > thr) c = Tc;
    else {
        float m = 0.f; c = 0;
        for (int t = 0; t < Tc; t++) { m += a; if (m > thr) { m -= thr; c++; } }
    }
    return (float)c;
}

// ---------------------------------------------------------------------------
// layer-0 prep: A' slots [v0,v0,v0,v1,v1,v2] of v=64*x gathered; B' slots
// [w0,w1,w2,w0,w1,w0]  (pairs (0,0)(0,1)(0,2)(1,0)(1,1)(2,0)).
__global__ void prep0_kernel(const float* __restrict__ x,
                             const int* __restrict__ axon,
                             const float* __restrict__ W) {
    int idx = blockIdx.x * blockDim.x + threadIdx.x;
    if (idx < Bc * Dc) {
        int b = idx >> 11, a = idx & 2047;
        unsigned u0, u1, u2;
        split3(64.0f * x[(b << 11) + axon[a]], u0, u1, u2);
        uint32_t* dst = (uint32_t*)(g_A + (size_t)b * KT0 + 6 * a);
        dst[0] = pk(u0, u0); dst[1] = pk(u0, u1); dst[2] = pk(u1, u2);
    } else {
        int i = idx - Bc * Dc;
        if (i >= Nc * Dc) return;
        int n = i >> 11, k = i & 2047;
        unsigned u0, u1, u2;
        split3(W[i], u0, u1, u2);
        uint32_t* dst = (uint32_t*)(g_B + (size_t)n * KT0 + 6 * k);
        dst[0] = pk(u0, u1); dst[1] = pk(u2, u0); dst[2] = pk(u1, u0);
    }
}

// layers>=1 prep: gather counts only (exact bf16), A at K=2048
__global__ void prep1g_kernel(const float* __restrict__ R,
                              const int* __restrict__ axon) {
    int idx = blockIdx.x * blockDim.x + threadIdx.x;
    if (idx >= Bc * Dc / 2) return;
    int b = idx >> 10, a = (idx & 1023) * 2;
    unsigned h0 = bfu(R[(b << 11) + axon[a]]);
    unsigned h1 = bfu(R[(b << 11) + axon[a + 1]]);
    *(uint32_t*)(g_A + (size_t)b * Dc + a) = pk(h0, h1);
}

// ---------------------------------------------------------------------------
// layer-0 GEMM (unchanged from round 10)
__global__ __launch_bounds__(GT, 1)
void gemm0_kernel() {
    extern __shared__ char smch[];
    const int tid = threadIdx.x;
    const int w = tid >> 5, lane = tid & 31;
    const int wm = w & 3, wn = w >> 2;
    const int g = lane >> 2, tig = lane & 3;
    const int bn = blockIdx.x * 64;
    const size_t k0 = (size_t)blockIdx.y * (KT0 / SPLITK);
    const uint32_t smb = (uint32_t)__cvta_generic_to_shared(smch);
    const int nPh = (KT0 / SPLITK) / 64;   // 48

    const __nv_bfloat16* srcs[6];
    uint32_t dsts[6];
    const int ch = tid & 7;
#pragma unroll
    for (int r = 0; r < 4; r++) {
        int row = (tid + r * GT) >> 3;
        srcs[r] = g_A + (size_t)row * KT0 + k0 + ch * 8;
        dsts[r] = smb + row * ROWB + ch * 16;
    }
#pragma unroll
    for (int r = 4; r < 6; r++) {
        int brow = (tid + (r - 4) * GT) >> 3;
        srcs[r] = g_B + (size_t)(bn + brow) * KT0 + k0 + ch * 8;
        dsts[r] = smb + ATILE + brow * ROWB + ch * 16;
    }
#define G0ISSUE(p, buf) do {                                        \
        uint32_t bo = (uint32_t)(buf) * BUF0;                       \
        _Pragma("unroll")                                           \
        for (int r = 0; r < 6; r++)                                 \
            cp16(dsts[r] + bo, srcs[r] + (size_t)(p) * 64);         \
        CP_COMMIT();                                                \
    } while (0)

    float acc[2][4][4], ks[2][4][4], kc[2][4][4];
#pragma unroll
    for (int mt = 0; mt < 2; mt++)
#pragma unroll
        for (int j = 0; j < 4; j++)
#pragma unroll
            for (int q = 0; q < 4; q++) {
                acc[mt][j][q] = 0.f; ks[mt][j][q] = 0.f; kc[mt][j][q] = 0.f;
            }

    G0ISSUE(0, 0);
    G0ISSUE(1, 1);

    for (int p = 0; p < nPh; p++) {
        if (p + 1 < nPh) { CP_WAIT(1); } else { CP_WAIT(0); }
        __syncthreads();
        const char* Ab = smch + (p & 1) * BUF0;
        const char* Bb = Ab + ATILE;
#pragma unroll
        for (int kk = 0; kk < 4; kk++) {
            uint32_t a[2][4];
#pragma unroll
            for (int mt = 0; mt < 2; mt++) {
                const char* ap = Ab + (wm * 32 + mt * 16 + g) * ROWB
                               + kk * 32 + tig * 4;
                a[mt][0] = lds32c(ap);
                a[mt][1] = lds32c(ap + 8 * ROWB);
                a[mt][2] = lds32c(ap + 16);
                a[mt][3] = lds32c(ap + 8 * ROWB + 16);
            }
#pragma unroll
            for (int j = 0; j < 4; j++) {
                const char* bp = Bb + (wn * 32 + j * 8 + g) * ROWB
                               + kk * 32 + tig * 4;
                uint32_t b0 = lds32c(bp);
                uint32_t b1 = lds32c(bp + 16);
                mma16816(acc[0][j], a[0], b0, b1);
                mma16816(acc[1][j], a[1], b0, b1);
            }
        }
        __syncthreads();
        if (p + 2 < nPh) G0ISSUE(p + 2, p & 1);

        if (p & 1) {
#pragma unroll
            for (int mt = 0; mt < 2; mt++)
#pragma unroll
                for (int j = 0; j < 4; j++)
#pragma unroll
                    for (int q = 0; q < 4; q++) {
                        float y = __fsub_rn(acc[mt][j][q], kc[mt][j][q]);
                        float t = __fadd_rn(ks[mt][j][q], y);
                        kc[mt][j][q] = __fsub_rn(__fsub_rn(t, ks[mt][j][q]), y);
                        ks[mt][j][q] = t;
                        acc[mt][j][q] = 0.f;
                    }
        }
    }
#undef G0ISSUE

    float* plane = g_P + (size_t)blockIdx.y * (Bc * Nc);
#pragma unroll
    for (int mt = 0; mt < 2; mt++)
#pragma unroll
        for (int j = 0; j < 4; j++) {
            int m = wm * 32 + mt * 16 + g;
            int n = bn + wn * 32 + j * 8 + 2 * tig;
            float r0 = __fsub_rn(ks[mt][j][0], kc[mt][j][0]);
            float r1 = __fsub_rn(ks[mt][j][1], kc[mt][j][1]);
            float r2 = __fsub_rn(ks[mt][j][2], kc[mt][j][2]);
            float r3 = __fsub_rn(ks[mt][j][3], kc[mt][j][3]);
            *(float2*)&plane[(size_t)m * Nc + n]       = make_float2(r0, r1);
            *(float2*)&plane[(size_t)(m + 8) * Nc + n] = make_float2(r2, r3);
        }
}

// ---------------------------------------------------------------------------
// layers>=1 GEMM, round-10 geometry (block 128m x 64n, splitK=4, Kahan fold
// per 64-col phase) but W fp32 is loaded ONCE here and split to the 3 bf16
// piece tiles in-kernel (same smem layout round 10's gemm1 consumed).
__global__ __launch_bounds__(GT, 1)
void gemm1s_kernel(const float* __restrict__ W) {
    extern __shared__ char smch[];
    const int tid = threadIdx.x;
    const int w = tid >> 5, lane = tid & 31;
    const int wm = w & 3, wn = w >> 2;
    const int g = lane >> 2, tig = lane & 3;
    const int bn = blockIdx.x * 64;
    const size_t k0 = (size_t)blockIdx.y * (Dc / SPLITK);   // 512-col slice
    const uint32_t smb = (uint32_t)__cvta_generic_to_shared(smch);
    const int nPh = (Dc / SPLITK) / 64;   // 8

    // A cp.async mapping (identical to round 10): 1024 chunks, 4 per thread
    const int ch = tid & 7;
    const __nv_bfloat16* sA[4];
    uint32_t dA[4];
#pragma unroll
    for (int r = 0; r < 4; r++) {
        int row = (tid + r * GT) >> 3;
        sA[r] = g_A + (size_t)row * Dc + k0 + ch * 8;
        dA[r] = smb + row * ROWB + ch * 16;
    }

    // W loader mapping: 64 rows x 64 cols fp32 per phase; thread t covers
    // row = t>>2, cols j*16 + (t&3)*4 .. +3 for j=0..3 (4 float4 loads).
    const int vrow = tid >> 2;
    const int vq   = tid & 3;
    const float* wp = W + (size_t)(bn + vrow) * Dc + k0 + vq * 4;
    const uint32_t bsts = smb + ATILE + vrow * ROWB + vq * 8;  // bf16 bytes

#define FA(p, buf) do {                                             \
        uint32_t bo = (uint32_t)(buf) * BUF1;                       \
        _Pragma("unroll")                                           \
        for (int r = 0; r < 4; r++)                                 \
            cp16(dA[r] + bo, sA[r] + (size_t)(p) * 64);             \
        CP_COMMIT();                                                \
    } while (0)

#define WLOAD(wr, p) do {                                           \
        _Pragma("unroll")                                           \
        for (int jj = 0; jj < 4; jj++)                              \
            wr[jj] = *(const float4*)(wp + (size_t)(p) * 64 + jj * 16); \
    } while (0)

    // split 16 floats -> 3 piece tiles; 4 x st.v2.b32 per piece
#define FB(buf, wr) do {                                            \
        uint32_t ba = bsts + (uint32_t)(buf) * BUF1;                \
        _Pragma("unroll")                                           \
        for (int jj = 0; jj < 4; jj++) {                            \
            float e4[4] = {wr[jj].x, wr[jj].y, wr[jj].z, wr[jj].w}; \
            unsigned q0[4], q1[4], q2[4];                           \
            _Pragma("unroll")                                       \
            for (int i = 0; i < 4; i++)                             \
                split3(e4[i], q0[i], q1[i], q2[i]);                 \
            uint32_t col = ba + jj * 32;                            \
            asm volatile("st.shared.v2.b32 [%0], {%1,%2};\n"        \
                :: "r"(col), "r"(pk(q0[0], q0[1])), "r"(pk(q0[2], q0[3]))); \
            asm volatile("st.shared.v2.b32 [%0], {%1,%2};\n"        \
                :: "r"(col + 64 * ROWB), "r"(pk(q1[0], q1[1])), "r"(pk(q1[2], q1[3]))); \
            asm volatile("st.shared.v2.b32 [%0], {%1,%2};\n"        \
                :: "r"(col + 128 * ROWB), "r"(pk(q2[0], q2[1])), "r"(pk(q2[2], q2[3]))); \
        }                                                           \
    } while (0)

    float acc[2][4][4], ks[2][4][4], kc[2][4][4];
#pragma unroll
    for (int mt = 0; mt < 2; mt++)
#pragma unroll
        for (int j = 0; j < 4; j++)
#pragma unroll
            for (int q = 0; q < 4; q++) {
                acc[mt][j][q] = 0.f; ks[mt][j][q] = 0.f; kc[mt][j][q] = 0.f;
            }

    // prologue: stage phases 0 and 1
    float4 wr[4];
    WLOAD(wr, 0); FB(0, wr); FA(0, 0);
    WLOAD(wr, 1); FB(1, wr); FA(1, 1);
    WLOAD(wr, 2);                       // nPh = 8 > 2

    for (int p = 0; p < nPh; p++) {
        if (p + 1 < nPh) { CP_WAIT(1); } else { CP_WAIT(0); }
        __syncthreads();                // A ready; prior FB stores visible
        const char* Ab = smch + (p & 1) * BUF1;
        const char* Bb = Ab + ATILE;
#pragma unroll
        for (int kk = 0; kk < 4; kk++) {
            uint32_t a[2][4];
#pragma unroll
            for (int mt = 0; mt < 2; mt++) {
                const char* ap = Ab + (wm * 32 + mt * 16 + g) * ROWB
                               + kk * 32 + tig * 4;
                a[mt][0] = lds32c(ap);
                a[mt][1] = lds32c(ap + 8 * ROWB);
                a[mt][2] = lds32c(ap + 16);
                a[mt][3] = lds32c(ap + 8 * ROWB + 16);
            }
#pragma unroll
            for (int pc = 0; pc < 3; pc++) {
#pragma unroll
                for (int j = 0; j < 4; j++) {
                    const char* bp = Bb + pc * (64 * ROWB)
                                   + (wn * 32 + j * 8 + g) * ROWB
                                   + kk * 32 + tig * 4;
                    uint32_t b0 = lds32c(bp);
                    uint32_t b1 = lds32c(bp + 16);
                    mma16816(acc[0][j], a[0], b0, b1);
                    mma16816(acc[1][j], a[1], b0, b1);
                }
            }
        }
        __syncthreads();                // all warps done with buf (p&1)
        if (p + 2 < nPh) {
            FB(p & 1, wr);              // stage W for phase p+2
            FA(p + 2, p & 1);
            if (p + 3 < nPh) WLOAD(wr, p + 3);
        }

        // Kahan fold every phase (identical to round 10)
#pragma unroll
        for (int mt = 0; mt < 2; mt++)
#pragma unroll
            for (int j = 0; j < 4; j++)
#pragma unroll
                for (int q = 0; q < 4; q++) {
                    float y = __fsub_rn(acc[mt][j][q], kc[mt][j][q]);
                    float t = __fadd_rn(ks[mt][j][q], y);
                    kc[mt][j][q] = __fsub_rn(__fsub_rn(t, ks[mt][j][q]), y);
                    ks[mt][j][q] = t;
                    acc[mt][j][q] = 0.f;
                }
    }
#undef FA
#undef FB
#undef WLOAD

    float* plane = g_P + (size_t)blockIdx.y * (Bc * Nc);
#pragma unroll
    for (int mt = 0; mt < 2; mt++)
#pragma unroll
        for (int j = 0; j < 4; j++) {
            int m = wm * 32 + mt * 16 + g;
            int n = bn + wn * 32 + j * 8 + 2 * tig;
            float r0 = __fsub_rn(ks[mt][j][0], kc[mt][j][0]);
            float r1 = __fsub_rn(ks[mt][j][1], kc[mt][j][1]);
            float r2 = __fsub_rn(ks[mt][j][2], kc[mt][j][2]);
            float r3 = __fsub_rn(ks[mt][j][3], kc[mt][j][3]);
            *(float2*)&plane[(size_t)m * Nc + n]       = make_float2(r0, r1);
            *(float2*)&plane[(size_t)(m + 8) * Nc + n] = make_float2(r2, r3);
        }
}

// ---------------------------------------------------------------------------
__global__ void scan_kernel(const float* __restrict__ thr, int l,
                            float* __restrict__ R) {
    int idx = blockIdx.x * blockDim.x + threadIdx.x;
    if (idx >= Bc * Nc) return;
    float e0 = g_P[0 * (Bc * Nc) + idx];
    float e1 = g_P[1 * (Bc * Nc) + idx];
    float e2 = g_P[2 * (Bc * Nc) + idx];
    float e3 = g_P[3 * (Bc * Nc) + idx];
    float s = __fadd_rn(__fadd_rn(e0, e1), __fadd_rn(e2, e3));
    R[idx] = spike_count(s * 0.015625f, thr[l]);   // /64 exact
}

__global__ void out_kernel(const float* __restrict__ R,
                           const int* __restrict__ out_idx,
                           float* __restrict__ out) {
    int idx = blockIdx.x * blockDim.x + threadIdx.x;
    if (idx >= Bc * OUTc) return;
    int b = idx >> 10, o = idx & 1023;
    out[idx] = R[(b << 11) + out_idx[o]];          // already counts
}

// ---------------------------------------------------------------------------
extern "C" void kernel_launch(void* const* d_in, const int* in_sizes, int n_in,
                              void* d_out, int out_size)
{
    const float* x       = (const float*)d_in[0];
    const float* W       = (const float*)d_in[1];
    const float* thr     = (const float*)d_in[2];
    const int*   axon    = (const int*)  d_in[3];
    const int*   out_idx = (const int*)  d_in[4];
    (void)in_sizes; (void)n_in; (void)out_size;

    cudaFuncSetAttribute(gemm0_kernel,
                         cudaFuncAttributeMaxDynamicSharedMemorySize, SMEM0);
    cudaFuncSetAttribute(gemm1s_kernel,
                         cudaFuncAttributeMaxDynamicSharedMemorySize, SMEM1);

    float *R0, *R1;
    cudaGetSymbolAddress((void**)&R0, g_R0);
    cudaGetSymbolAddress((void**)&R1, g_R1);

    // layer 0 (round-10 path, measured rel_err 0.0)
    prep0_kernel<<<(Bc * Dc + Nc * Dc + 255) / 256, 256>>>(x, axon, W);
    gemm0_kernel<<<dim3(32, SPLITK), GT, SMEM0>>>();
    scan_kernel<<<1024, 256>>>(thr, 0, R0);

    const float* rin = R0;
    for (int l = 1; l < 4; l++) {
        prep1g_kernel<<<512, 256>>>(rin, axon + l * Dc);
        gemm1s_kernel<<<dim3(32, SPLITK), GT, SMEM1>>>(
            W + (size_t)l * Nc * Dc);
        float* rout = (l & 1) ? R1 : R0;
        scan_kernel<<<1024, 256>>>(thr, l, rout);
        rin = rout;
    }
    out_kernel<<<512, 256>>>(rin, out_idx, (float*)d_out);
}

// round 13
// speedup vs baseline: 1.5227x; 1.2632x over previous
#include <cuda_runtime.h>
#include <cuda_bf16.h>
#include <cstdint>

// ---------------------------------------------------------------------------
// StableSpikingCoreFlow, round 13 = round 12 (139.7us, rel_err 0.0) with the
// proven in-kernel-W-split transformation applied to layer 0 too:
//  - prep0a: gather + split 64*x into 3 bf16 piece matrices (tiny).
//  - gemm0s: round-12 geometry (128m x 64n, splitK=4), W fp32 read once and
//    split in-kernel; MMA over the proven 6 piece-pairs
//    (a0b0,a0b1,a0b2,a1b0,a1b1,a2b0); Kahan fold per 64-col phase.
// Layers 1-3 and scan/out identical to round 12.
// ---------------------------------------------------------------------------

#define Bc 128
#define Dc 2048
#define Nc 2048
#define Tc 64
#define OUTc 1024
#define SPLITK 4
#define GT  256

#define ROWB 144             // 64 bf16 (128B) + 16B pad
#define ATILE (128 * ROWB)   // 18432 B
#define BT64  (64 * ROWB)    //  9216 B
// layers>=1 gemm (round-12 gemm1s)
#define BUF1  (ATILE + 3 * BT64)
#define SMEM1 (2 * BUF1)     // 92160 B
// layer-0 gemm: 3 A-piece tiles + 3 B-piece tiles per buffer
#define BUFG  (3 * ATILE + 3 * BT64)   // 82944 B
#define SMEMG (2 * BUFG)               // 165888 B

#define APIECE (Bc * Dc)     // elements per A piece matrix

__device__ __nv_bfloat16 g_A[3 * APIECE];   // layer0: 3 pieces; layers>=1: piece 0
__device__ float g_P[SPLITK * Bc * Nc];
__device__ float g_R0[Bc * Nc];
__device__ float g_R1[Bc * Nc];

// ---------------------------------------------------------------------------
__device__ __forceinline__ void cp16(uint32_t dst, const void* src) {
    asm volatile("cp.async.cg.shared.global [%0], [%1], 16;\n" :: "r"(dst), "l"(src));
}
#define CP_COMMIT() asm volatile("cp.async.commit_group;\n" ::: "memory")
#define CP_WAIT(n)  asm volatile("cp.async.wait_group %0;\n" :: "n"(n) : "memory")

__device__ __forceinline__ void mma16816(float* c, const uint32_t* a,
                                         uint32_t b0, uint32_t b1) {
    asm volatile(
        "mma.sync.aligned.m16n8k16.row.col.f32.bf16.bf16.f32 "
        "{%0,%1,%2,%3},{%4,%5,%6,%7},{%8,%9},{%0,%1,%2,%3};\n"
        : "+f"(c[0]), "+f"(c[1]), "+f"(c[2]), "+f"(c[3])
        : "r"(a[0]), "r"(a[1]), "r"(a[2]), "r"(a[3]), "r"(b0), "r"(b1));
}

__device__ __forceinline__ uint32_t lds32c(const char* p) {
    return *(const uint32_t*)p;
}

__device__ __forceinline__ float bfround(float v) {
    return __bfloat162float(__float2bfloat16_rn(v));
}
__device__ __forceinline__ unsigned bfu(float v) {
    return (unsigned)__bfloat16_as_ushort(__float2bfloat16_rn(v));
}
__device__ __forceinline__ uint32_t pk(unsigned lo, unsigned hi) {
    return lo | (hi << 16);
}
// v = p0+p1+p2 + O(2^-25 v); residual subtractions exact
__device__ __forceinline__ void split3(float v, unsigned& u0, unsigned& u1,
                                       unsigned& u2) {
    float r1 = v - bfround(v);
    float r2 = r1 - bfround(r1);
    u0 = bfu(v); u1 = bfu(r1); u2 = bfu(r2);
}

// exact fp32 semantics of the reference spike scan; returns COUNT (0..64)
__device__ __forceinline__ float spike_count(float a, float thr) {
    int c;
    if (a <= 0.f) c = 0;
    else if (a > thr) c = Tc;
    else {
        float m = 0.f; c = 0;
        for (int t = 0; t < Tc; t++) { m += a; if (m > thr) { m -= thr; c++; } }
    }
    return (float)c;
}

// ---------------------------------------------------------------------------
// layer-0 prep: gather + split 64*x into 3 bf16 piece matrices (2 k/thread)
__global__ void prep0a_kernel(const float* __restrict__ x,
                              const int* __restrict__ axon) {
    int idx = blockIdx.x * blockDim.x + threadIdx.x;
    if (idx >= Bc * Dc / 2) return;
    int b = idx >> 10, a = (idx & 1023) * 2;
    unsigned p0, p1, p2, q0, q1, q2;
    split3(64.0f * x[(b << 11) + axon[a]],     p0, p1, p2);
    split3(64.0f * x[(b << 11) + axon[a + 1]], q0, q1, q2);
    size_t off = (size_t)b * Dc + a;
    *(uint32_t*)(g_A + off)              = pk(p0, q0);
    *(uint32_t*)(g_A + APIECE + off)     = pk(p1, q1);
    *(uint32_t*)(g_A + 2 * APIECE + off) = pk(p2, q2);
}

// layers>=1 prep: gather counts only (exact bf16) into piece 0
__global__ void prep1g_kernel(const float* __restrict__ R,
                              const int* __restrict__ axon) {
    int idx = blockIdx.x * blockDim.x + threadIdx.x;
    if (idx >= Bc * Dc / 2) return;
    int b = idx >> 10, a = (idx & 1023) * 2;
    unsigned h0 = bfu(R[(b << 11) + axon[a]]);
    unsigned h1 = bfu(R[(b << 11) + axon[a + 1]]);
    *(uint32_t*)(g_A + (size_t)b * Dc + a) = pk(h0, h1);
}

// ---------------------------------------------------------------------------
// layer-0 GEMM: 6 piece-pairs, W split in-kernel, splitK=4, Kahan per phase.
__global__ __launch_bounds__(GT, 1)
void gemm0s_kernel(const float* __restrict__ W) {
    extern __shared__ char smch[];
    const int tid = threadIdx.x;
    const int w = tid >> 5, lane = tid & 31;
    const int wm = w & 3, wn = w >> 2;
    const int g = lane >> 2, tig = lane & 3;
    const int bn = blockIdx.x * 64;
    const size_t k0 = (size_t)blockIdx.y * (Dc / SPLITK);
    const uint32_t smb = (uint32_t)__cvta_generic_to_shared(smch);
    const int nPh = (Dc / SPLITK) / 64;   // 8

    // A piece cp.async mapping: per piece 1024 chunks, 4/thread
    const int ch = tid & 7;
    const int arow = tid >> 3;
    const uint32_t dAbase = smb + arow * ROWB + ch * 16;
    const size_t sAoff = (size_t)arow * Dc + k0 + ch * 8;

    // W loader: 64 rows x 64 cols fp32/phase; thread t: row t>>2, 4 float4
    const int vrow = tid >> 2;
    const int vq   = tid & 3;
    const float* wp = W + (size_t)(bn + vrow) * Dc + k0 + vq * 4;
    const uint32_t bsts = smb + 3 * ATILE + vrow * ROWB + vq * 8;

#define FA0(p, buf) do {                                                     \
        uint32_t bo = (uint32_t)(buf) * BUFG;                                \
        _Pragma("unroll")                                                    \
        for (int pc = 0; pc < 3; pc++)                                       \
            _Pragma("unroll")                                                \
            for (int r = 0; r < 4; r++)                                      \
                cp16(dAbase + bo + pc * ATILE + r * (32 * ROWB),             \
                     g_A + pc * APIECE + sAoff + (size_t)r * (32 * Dc)       \
                         + (size_t)(p) * 64);                                \
        CP_COMMIT();                                                         \
    } while (0)

#define WLOAD(wr, p) do {                                                    \
        _Pragma("unroll")                                                    \
        for (int jj = 0; jj < 4; jj++)                                       \
            wr[jj] = *(const float4*)(wp + (size_t)(p) * 64 + jj * 16);      \
    } while (0)

#define FB0(buf, wr) do {                                                    \
        uint32_t ba = bsts + (uint32_t)(buf) * BUFG;                         \
        _Pragma("unroll")                                                    \
        for (int jj = 0; jj < 4; jj++) {                                     \
            float e4[4] = {wr[jj].x, wr[jj].y, wr[jj].z, wr[jj].w};          \
            unsigned q0[4], q1[4], q2[4];                                    \
            _Pragma("unroll")                                                \
            for (int i = 0; i < 4; i++)                                      \
                split3(e4[i], q0[i], q1[i], q2[i]);                          \
            uint32_t col = ba + jj * 32;                                     \
            asm volatile("st.shared.v2.b32 [%0], {%1,%2};\n"                 \
                :: "r"(col), "r"(pk(q0[0], q0[1])), "r"(pk(q0[2], q0[3]))); \
            asm volatile("st.shared.v2.b32 [%0], {%1,%2};\n"                 \
                :: "r"(col + BT64), "r"(pk(q1[0], q1[1])), "r"(pk(q1[2], q1[3]))); \
            asm volatile("st.shared.v2.b32 [%0], {%1,%2};\n"                 \
                :: "r"(col + 2 * BT64), "r"(pk(q2[0], q2[1])), "r"(pk(q2[2], q2[3]))); \
        }                                                                    \
    } while (0)

    float acc[2][4][4], ks[2][4][4], kc[2][4][4];
#pragma unroll
    for (int mt = 0; mt < 2; mt++)
#pragma unroll
        for (int j = 0; j < 4; j++)
#pragma unroll
            for (int q = 0; q < 4; q++) {
                acc[mt][j][q] = 0.f; ks[mt][j][q] = 0.f; kc[mt][j][q] = 0.f;
            }

    float4 wr[4];
    WLOAD(wr, 0); FB0(0, wr); FA0(0, 0);
    WLOAD(wr, 1); FB0(1, wr); FA0(1, 1);
    WLOAD(wr, 2);

    for (int p = 0; p < nPh; p++) {
        if (p + 1 < nPh) { CP_WAIT(1); } else { CP_WAIT(0); }
        __syncthreads();
        const char* Ab = smch + (p & 1) * BUFG;
        const char* Bb = Ab + 3 * ATILE;
#pragma unroll
        for (int kk = 0; kk < 4; kk++) {
            uint32_t a[3][2][4];
#pragma unroll
            for (int pc = 0; pc < 3; pc++)
#pragma unroll
                for (int mt = 0; mt < 2; mt++) {
                    const char* ap = Ab + pc * ATILE
                                   + (wm * 32 + mt * 16 + g) * ROWB
                                   + kk * 32 + tig * 4;
                    a[pc][mt][0] = lds32c(ap);
                    a[pc][mt][1] = lds32c(ap + 8 * ROWB);
                    a[pc][mt][2] = lds32c(ap + 16);
                    a[pc][mt][3] = lds32c(ap + 8 * ROWB + 16);
                }
#pragma unroll
            for (int j = 0; j < 4; j++) {
                const char* brow = Bb + (wn * 32 + j * 8 + g) * ROWB
                                 + kk * 32 + tig * 4;
                uint32_t b00 = lds32c(brow);
                uint32_t b01 = lds32c(brow + 16);
                uint32_t b10 = lds32c(brow + BT64);
                uint32_t b11 = lds32c(brow + BT64 + 16);
                uint32_t b20 = lds32c(brow + 2 * BT64);
                uint32_t b21 = lds32c(brow + 2 * BT64 + 16);
#pragma unroll
                for (int mt = 0; mt < 2; mt++) {
                    mma16816(acc[mt][j], a[0][mt], b00, b01);  // a0*w0
                    mma16816(acc[mt][j], a[0][mt], b10, b11);  // a0*w1
                    mma16816(acc[mt][j], a[0][mt], b20, b21);  // a0*w2
                    mma16816(acc[mt][j], a[1][mt], b00, b01);  // a1*w0
                    mma16816(acc[mt][j], a[1][mt], b10, b11);  // a1*w1
                    mma16816(acc[mt][j], a[2][mt], b00, b01);  // a2*w0
                }
            }
        }
        __syncthreads();
        if (p + 2 < nPh) {
            FB0(p & 1, wr);
            FA0(p + 2, p & 1);
            if (p + 3 < nPh) WLOAD(wr, p + 3);
        }

        // Kahan fold per phase (24 hw adds per chunk, proven class)
#pragma unroll
        for (int mt = 0; mt < 2; mt++)
#pragma unroll
            for (int j = 0; j < 4; j++)
#pragma unroll
                for (int q = 0; q < 4; q++) {
                    float y = __fsub_rn(acc[mt][j][q], kc[mt][j][q]);
                    float t = __fadd_rn(ks[mt][j][q], y);
                    kc[mt][j][q] = __fsub_rn(__fsub_rn(t, ks[mt][j][q]), y);
                    ks[mt][j][q] = t;
                    acc[mt][j][q] = 0.f;
                }
    }
#undef FA0
#undef FB0
#undef WLOAD

    float* plane = g_P + (size_t)blockIdx.y * (Bc * Nc);
#pragma unroll
    for (int mt = 0; mt < 2; mt++)
#pragma unroll
        for (int j = 0; j < 4; j++) {
            int m = wm * 32 + mt * 16 + g;
            int n = bn + wn * 32 + j * 8 + 2 * tig;
            float r0 = __fsub_rn(ks[mt][j][0], kc[mt][j][0]);
            float r1 = __fsub_rn(ks[mt][j][1], kc[mt][j][1]);
            float r2 = __fsub_rn(ks[mt][j][2], kc[mt][j][2]);
            float r3 = __fsub_rn(ks[mt][j][3], kc[mt][j][3]);
            *(float2*)&plane[(size_t)m * Nc + n]       = make_float2(r0, r1);
            *(float2*)&plane[(size_t)(m + 8) * Nc + n] = make_float2(r2, r3);
        }
}

// ---------------------------------------------------------------------------
// layers>=1 GEMM: identical to round 12's gemm1s (W split in-kernel)
__global__ __launch_bounds__(GT, 1)
void gemm1s_kernel(const float* __restrict__ W) {
    extern __shared__ char smch[];
    const int tid = threadIdx.x;
    const int w = tid >> 5, lane = tid & 31;
    const int wm = w & 3, wn = w >> 2;
    const int g = lane >> 2, tig = lane & 3;
    const int bn = blockIdx.x * 64;
    const size_t k0 = (size_t)blockIdx.y * (Dc / SPLITK);
    const uint32_t smb = (uint32_t)__cvta_generic_to_shared(smch);
    const int nPh = (Dc / SPLITK) / 64;   // 8

    const int ch = tid & 7;
    const __nv_bfloat16* sA[4];
    uint32_t dA[4];
#pragma unroll
    for (int r = 0; r < 4; r++) {
        int row = (tid + r * GT) >> 3;
        sA[r] = g_A + (size_t)row * Dc + k0 + ch * 8;
        dA[r] = smb + row * ROWB + ch * 16;
    }

    const int vrow = tid >> 2;
    const int vq   = tid & 3;
    const float* wp = W + (size_t)(bn + vrow) * Dc + k0 + vq * 4;
    const uint32_t bsts = smb + ATILE + vrow * ROWB + vq * 8;

#define FA(p, buf) do {                                             \
        uint32_t bo = (uint32_t)(buf) * BUF1;                       \
        _Pragma("unroll")                                           \
        for (int r = 0; r < 4; r++)                                 \
            cp16(dA[r] + bo, sA[r] + (size_t)(p) * 64);             \
        CP_COMMIT();                                                \
    } while (0)

#define WLOAD(wr, p) do {                                           \
        _Pragma("unroll")                                           \
        for (int jj = 0; jj < 4; jj++)                              \
            wr[jj] = *(const float4*)(wp + (size_t)(p) * 64 + jj * 16); \
    } while (0)

#define FB(buf, wr) do {                                            \
        uint32_t ba = bsts + (uint32_t)(buf) * BUF1;                \
        _Pragma("unroll")                                           \
        for (int jj = 0; jj < 4; jj++) {                            \
            float e4[4] = {wr[jj].x, wr[jj].y, wr[jj].z, wr[jj].w}; \
            unsigned q0[4], q1[4], q2[4];                           \
            _Pragma("unroll")                                       \
            for (int i = 0; i < 4; i++)                             \
                split3(e4[i], q0[i], q1[i], q2[i]);                 \
            uint32_t col = ba + jj * 32;                            \
            asm volatile("st.shared.v2.b32 [%0], {%1,%2};\n"        \
                :: "r"(col), "r"(pk(q0[0], q0[1])), "r"(pk(q0[2], q0[3]))); \
            asm volatile("st.shared.v2.b32 [%0], {%1,%2};\n"        \
                :: "r"(col + 64 * ROWB), "r"(pk(q1[0], q1[1])), "r"(pk(q1[2], q1[3]))); \
            asm volatile("st.shared.v2.b32 [%0], {%1,%2};\n"        \
                :: "r"(col + 128 * ROWB), "r"(pk(q2[0], q2[1])), "r"(pk(q2[2], q2[3]))); \
        }                                                           \
    } while (0)

    float acc[2][4][4], ks[2][4][4], kc[2][4][4];
#pragma unroll
    for (int mt = 0; mt < 2; mt++)
#pragma unroll
        for (int j = 0; j < 4; j++)
#pragma unroll
            for (int q = 0; q < 4; q++) {
                acc[mt][j][q] = 0.f; ks[mt][j][q] = 0.f; kc[mt][j][q] = 0.f;
            }

    float4 wr[4];
    WLOAD(wr, 0); FB(0, wr); FA(0, 0);
    WLOAD(wr, 1); FB(1, wr); FA(1, 1);
    WLOAD(wr, 2);

    for (int p = 0; p < nPh; p++) {
        if (p + 1 < nPh) { CP_WAIT(1); } else { CP_WAIT(0); }
        __syncthreads();
        const char* Ab = smch + (p & 1) * BUF1;
        const char* Bb = Ab + ATILE;
#pragma unroll
        for (int kk = 0; kk < 4; kk++) {
            uint32_t a[2][4];
#pragma unroll
            for (int mt = 0; mt < 2; mt++) {
                const char* ap = Ab + (wm * 32 + mt * 16 + g) * ROWB
                               + kk * 32 + tig * 4;
                a[mt][0] = lds32c(ap);
                a[mt][1] = lds32c(ap + 8 * ROWB);
                a[mt][2] = lds32c(ap + 16);
                a[mt][3] = lds32c(ap + 8 * ROWB + 16);
            }
#pragma unroll
            for (int pc = 0; pc < 3; pc++) {
#pragma unroll
                for (int j = 0; j < 4; j++) {
                    const char* bp = Bb + pc * (64 * ROWB)
                                   + (wn * 32 + j * 8 + g) * ROWB
                                   + kk * 32 + tig * 4;
                    uint32_t b0 = lds32c(bp);
                    uint32_t b1 = lds32c(bp + 16);
                    mma16816(acc[0][j], a[0], b0, b1);
                    mma16816(acc[1][j], a[1], b0, b1);
                }
            }
        }
        __syncthreads();
        if (p + 2 < nPh) {
            FB(p & 1, wr);
            FA(p + 2, p & 1);
            if (p + 3 < nPh) WLOAD(wr, p + 3);
        }

#pragma unroll
        for (int mt = 0; mt < 2; mt++)
#pragma unroll
            for (int j = 0; j < 4; j++)
#pragma unroll
                for (int q = 0; q < 4; q++) {
                    float y = __fsub_rn(acc[mt][j][q], kc[mt][j][q]);
                    float t = __fadd_rn(ks[mt][j][q], y);
                    kc[mt][j][q] = __fsub_rn(__fsub_rn(t, ks[mt][j][q]), y);
                    ks[mt][j][q] = t;
                    acc[mt][j][q] = 0.f;
                }
    }
#undef FA
#undef FB
#undef WLOAD

    float* plane = g_P + (size_t)blockIdx.y * (Bc * Nc);
#pragma unroll
    for (int mt = 0; mt < 2; mt++)
#pragma unroll
        for (int j = 0; j < 4; j++) {
            int m = wm * 32 + mt * 16 + g;
            int n = bn + wn * 32 + j * 8 + 2 * tig;
            float r0 = __fsub_rn(ks[mt][j][0], kc[mt][j][0]);
            float r1 = __fsub_rn(ks[mt][j][1], kc[mt][j][1]);
            float r2 = __fsub_rn(ks[mt][j][2], kc[mt][j][2]);
            float r3 = __fsub_rn(ks[mt][j][3], kc[mt][j][3]);
            *(float2*)&plane[(size_t)m * Nc + n]       = make_float2(r0, r1);
            *(float2*)&plane[(size_t)(m + 8) * Nc + n] = make_float2(r2, r3);
        }
}

// ---------------------------------------------------------------------------
__global__ void scan_kernel(const float* __restrict__ thr, int l,
                            float* __restrict__ R) {
    int idx = blockIdx.x * blockDim.x + threadIdx.x;
    if (idx >= Bc * Nc) return;
    float e0 = g_P[0 * (Bc * Nc) + idx];
    float e1 = g_P[1 * (Bc * Nc) + idx];
    float e2 = g_P[2 * (Bc * Nc) + idx];
    float e3 = g_P[3 * (Bc * Nc) + idx];
    float s = __fadd_rn(__fadd_rn(e0, e1), __fadd_rn(e2, e3));
    R[idx] = spike_count(s * 0.015625f, thr[l]);   // /64 exact
}

__global__ void out_kernel(const float* __restrict__ R,
                           const int* __restrict__ out_idx,
                           float* __restrict__ out) {
    int idx = blockIdx.x * blockDim.x + threadIdx.x;
    if (idx >= Bc * OUTc) return;
    int b = idx >> 10, o = idx & 1023;
    out[idx] = R[(b << 11) + out_idx[o]];          // already counts
}

// ---------------------------------------------------------------------------
extern "C" void kernel_launch(void* const* d_in, const int* in_sizes, int n_in,
                              void* d_out, int out_size)
{
    const float* x       = (const float*)d_in[0];
    const float* W       = (const float*)d_in[1];
    const float* thr     = (const float*)d_in[2];
    const int*   axon    = (const int*)  d_in[3];
    const int*   out_idx = (const int*)  d_in[4];
    (void)in_sizes; (void)n_in; (void)out_size;

    cudaFuncSetAttribute(gemm0s_kernel,
                         cudaFuncAttributeMaxDynamicSharedMemorySize, SMEMG);
    cudaFuncSetAttribute(gemm1s_kernel,
                         cudaFuncAttributeMaxDynamicSharedMemorySize, SMEM1);

    float *R0, *R1;
    cudaGetSymbolAddress((void**)&R0, g_R0);
    cudaGetSymbolAddress((void**)&R1, g_R1);

    // layer 0
    prep0a_kernel<<<512, 256>>>(x, axon);
    gemm0s_kernel<<<dim3(32, SPLITK), GT, SMEMG>>>(W);
    scan_kernel<<<1024, 256>>>(thr, 0, R0);

    const float* rin = R0;
    for (int l = 1; l < 4; l++) {
        prep1g_kernel<<<512, 256>>>(rin, axon + l * Dc);
        gemm1s_kernel<<<dim3(32, SPLITK), GT, SMEM1>>>(
            W + (size_t)l * Nc * Dc);
        float* rout = (l & 1) ? R1 : R0;
        scan_kernel<<<1024, 256>>>(thr, l, rout);
        rin = rout;
    }
    out_kernel<<<512, 256>>>(rin, out_idx, (float*)d_out);
}